// round 13
// baseline (speedup 1.0000x reference)
#include <cuda_runtime.h>

// ---------------------------------------------------------------------------
// MSGMS loss, 4-scale pyramid.
//  Kernel 1 (graypyr_k): fused grayscale + avg-pool pyramid (~68% DRAM, floor).
//  Kernel 2 (gms_strip_k): register-rolling strips, ZERO smem staging.
//     Each thread: 4 output cols x 8 output rows; walks rows keeping
//     3 gray rows + 3 median rows in registers; gray read straight from
//     L2-resident g_gray via guarded LDG.128. No barriers, no LDS stages.
//  Kernel 3 (finalize_k): fixed-order deterministic sum of block partials.
// ---------------------------------------------------------------------------

#define C_GMS 0.0026f

static constexpr int NB   = 16;
static constexpr int HW0  = 512 * 512;
static constexpr int OFF0 = 0;
static constexpr int OFF1 = OFF0 + 16 * 512 * 512;
static constexpr int OFF2 = OFF1 + 16 * 256 * 256;
static constexpr int OFF3 = OFF2 + 16 * 128 * 128;
static constexpr int GTOT = OFF3 + 16 * 64 * 64;

// strips: 4 output cols x 8 output rows, one thread each
static constexpr int T0 = NB * (512 / 4) * (512 / 8);   // 131072
static constexpr int T1 = NB * (256 / 4) * (256 / 8);   // 32768
static constexpr int T2 = NB * (128 / 4) * (128 / 8);   // 8192
static constexpr int T3 = NB * (64 / 4) * (64 / 8);     // 2048
static constexpr int TTOT = T0 + T1 + T2 + T3;          // 174080
static constexpr int NBLK = TTOT / 128;                 // 1360 blocks

__device__ float  g_gray[2][GTOT];
__device__ double g_partial[NBLK];

// ---------------------------------------------------------------------------
// Kernel 1: grayscale + pooled pyramid (register-fused gray->L1, 10KB smem).
// ---------------------------------------------------------------------------
__global__ __launch_bounds__(256) void graypyr_k(const float* __restrict__ Ii,
                                                 const float* __restrict__ Ir) {
    const int s = blockIdx.x;   // stripe 0..63 (L0 rows 8s..8s+7)
    const int b = blockIdx.y;   // batch
    const int tid = threadIdx.x;
    __shared__ float s1[2][4][256];
    __shared__ float s2[2][2][128];
    const float inv3 = 1.0f / 3.0f;

    for (int i = tid; i < 1024; i += 256) {
        int img = i >> 9;
        int rem = i & 511;
        int r1  = rem >> 7;      // L1 row 0..3
        int k   = rem & 127;     // col-pair (L0 cols 4k..4k+3)
        const float* base = (img ? Ir : Ii) + (size_t)b * 3 * HW0
                            + (size_t)(s * 8 + 2 * r1) * 512 + 4 * k;
        float4 a0 = *(const float4*)base;
        float4 a1 = *(const float4*)(base + HW0);
        float4 a2 = *(const float4*)(base + 2 * HW0);
        float4 g0 = { (a0.x + a1.x + a2.x) * inv3, (a0.y + a1.y + a2.y) * inv3,
                      (a0.z + a1.z + a2.z) * inv3, (a0.w + a1.w + a2.w) * inv3 };
        const float* baseb = base + 512;
        float4 c0 = *(const float4*)baseb;
        float4 c1 = *(const float4*)(baseb + HW0);
        float4 c2 = *(const float4*)(baseb + 2 * HW0);
        float4 g1 = { (c0.x + c1.x + c2.x) * inv3, (c0.y + c1.y + c2.y) * inv3,
                      (c0.z + c1.z + c2.z) * inv3, (c0.w + c1.w + c2.w) * inv3 };
        float* L0 = &g_gray[img][(size_t)b * HW0 + (size_t)(s * 8 + 2 * r1) * 512 + 4 * k];
        *(float4*)L0         = g0;
        *(float4*)(L0 + 512) = g1;
        float2 l1 = { (g0.x + g0.y + g1.x + g1.y) * 0.25f,
                      (g0.z + g0.w + g1.z + g1.w) * 0.25f };
        *(float2*)&s1[img][r1][2 * k] = l1;
        *(float2*)&g_gray[img][OFF1 + (size_t)b * 256 * 256 + (size_t)(s * 4 + r1) * 256 + 2 * k] = l1;
    }
    __syncthreads();

    for (int i = tid; i < 512; i += 256) {
        int img = i >> 8;
        int rem = i & 255;
        int r   = rem >> 7;
        int c   = rem & 127;
        float2 t0 = *(const float2*)&s1[img][2 * r][2 * c];
        float2 t1 = *(const float2*)&s1[img][2 * r + 1][2 * c];
        float v = (t0.x + t0.y + t1.x + t1.y) * 0.25f;
        s2[img][r][c] = v;
        g_gray[img][OFF2 + (size_t)b * 128 * 128 + (size_t)(s * 2 + r) * 128 + c] = v;
    }
    __syncthreads();

    if (tid < 128) {
        int img = tid >> 6;
        int c   = tid & 63;
        float2 t0 = *(const float2*)&s2[img][0][2 * c];
        float2 t1 = *(const float2*)&s2[img][1][2 * c];
        float v = (t0.x + t0.y + t1.x + t1.y) * 0.25f;
        g_gray[img][OFF3 + (size_t)b * 64 * 64 + (size_t)s * 64 + c] = v;
    }
}

// ---------------------------------------------------------------------------
// Register-rolling GMS strips
// ---------------------------------------------------------------------------
__device__ __forceinline__ float med3f(float a, float b, float c) {
    return fmaxf(fminf(a, b), fminf(fmaxf(a, b), c));
}
__device__ __forceinline__ void sort3f(float& a, float& b, float& c) {
    float t;
    t = fminf(a, b); b = fmaxf(a, b); a = t;
    t = fminf(b, c); c = fmaxf(b, c); b = t;
    t = fminf(a, b); b = fmaxf(a, b); a = t;
}

// load gray cols c0-4..c0+7 (12 floats, 3 aligned quads) of row y; zero OOB.
// Quads are always fully in-bounds or fully out (c0 % 4 == 0, W % 8 == 0).
template <int H, int W>
__device__ __forceinline__ void load_row(const float* __restrict__ g, int y,
                                         int c0, float* out12) {
#pragma unroll
    for (int q = 0; q < 3; q++) {
        int qc = c0 - 4 + 4 * q;
        float4 v = {0.f, 0.f, 0.f, 0.f};
        if ((unsigned)y < (unsigned)H && (unsigned)qc < (unsigned)W)
            v = *(const float4*)(g + (size_t)y * W + qc);
        out12[4 * q + 0] = v.x; out12[4 * q + 1] = v.y;
        out12[4 * q + 2] = v.z; out12[4 * q + 3] = v.w;
    }
}

// median-of-9 row: inputs = 3 gray rows (12 cols, use local cols 3..10),
// output = 6 medians (med cols c0..c0+5).
__device__ __forceinline__ void med_row6(const float* a, const float* b,
                                         const float* c, float* m) {
    float lo[8], mi[8], hi[8];
#pragma unroll
    for (int j = 0; j < 8; j++) {
        float v0 = a[j + 3], v1 = b[j + 3], v2 = c[j + 3];
        sort3f(v0, v1, v2);
        lo[j] = v0; mi[j] = v1; hi[j] = v2;
    }
#pragma unroll
    for (int t = 0; t < 6; t++) {
        float L  = fmaxf(fmaxf(lo[t], lo[t + 1]), lo[t + 2]);
        float M  = med3f(mi[t], mi[t + 1], mi[t + 2]);
        float Hh = fminf(fminf(hi[t], hi[t + 1]), hi[t + 2]);
        m[t] = med3f(L, M, Hh);
    }
}

template <int H, int W>
__device__ __forceinline__ float gms_strip(int local, int off) {
    constexpr int CS = W / 4;       // col-strips per image (pow2)
    constexpr int BD = H / 8;       // row-bands (pow2; covers H-2 output rows)
    const int b    = local / (CS * BD);
    const int rem  = local % (CS * BD);
    const int band = rem / CS;
    const int k    = rem % CS;
    const int c0 = 4 * k, j0 = 8 * band;

    const float* __restrict__ g0 = &g_gray[0][off + (size_t)b * H * W];
    const float* __restrict__ g1 = &g_gray[1][off + (size_t)b * H * W];

    float gA[2][12], gB[2][12], gN[2][12], gM[2][12];
    float m0[2][6], m1[2][6], m2[2][6];

    // prologue: med rows j0, j0+1
    load_row<H, W>(g0, j0 - 1, c0, gM[0]); load_row<H, W>(g1, j0 - 1, c0, gM[1]);
    load_row<H, W>(g0, j0,     c0, gA[0]); load_row<H, W>(g1, j0,     c0, gA[1]);
    load_row<H, W>(g0, j0 + 1, c0, gB[0]); load_row<H, W>(g1, j0 + 1, c0, gB[1]);
    med_row6(gM[0], gA[0], gB[0], m0[0]);  med_row6(gM[1], gA[1], gB[1], m0[1]);
    load_row<H, W>(g0, j0 + 2, c0, gN[0]); load_row<H, W>(g1, j0 + 2, c0, gN[1]);
    med_row6(gA[0], gB[0], gN[0], m1[0]);  med_row6(gA[1], gB[1], gN[1], m1[1]);
#pragma unroll
    for (int x = 0; x < 12; x++) {
        gA[0][x] = gB[0][x]; gA[1][x] = gB[1][x];
        gB[0][x] = gN[0][x]; gB[1][x] = gN[1][x];
    }

    const float C9 = 9.0f * C_GMS;
    float acc = 0.0f;
#pragma unroll
    for (int jj = 0; jj < 8; jj++) {
        const int j = j0 + jj;
        load_row<H, W>(g0, j + 3, c0, gN[0]); load_row<H, W>(g1, j + 3, c0, gN[1]);
        med_row6(gA[0], gB[0], gN[0], m2[0]); med_row6(gA[1], gB[1], gN[1], m2[1]);

        float t[2][4];
#pragma unroll
        for (int im = 0; im < 2; im++) {
            float cs[6];
#pragma unroll
            for (int c = 0; c < 6; c++) cs[c] = m0[im][c] + m1[im][c] + m2[im][c];
#pragma unroll
            for (int x = 0; x < 4; x++) {
                float gx = cs[x + 2] - cs[x];
                float gy = (m0[im][x] + m0[im][x + 1] + m0[im][x + 2])
                         - (m2[im][x] + m2[im][x + 1] + m2[im][x + 2]);
                t[im][x] = gx * gx + gy * gy;
            }
        }
        if (j <= H - 3) {
#pragma unroll
            for (int x = 0; x < 4; x++) {
                if (c0 + x <= W - 3) {
                    float p = t[0][x] * t[1][x];
                    float s = p * rsqrtf(p + 1e-30f);     // sqrt(p), 0-safe
                    acc += 1.0f - __fdividef(2.0f * s + C9, t[0][x] + t[1][x] + C9);
                }
            }
        }
        // shift state (register renaming under full unroll)
#pragma unroll
        for (int c = 0; c < 6; c++) {
            m0[0][c] = m1[0][c]; m0[1][c] = m1[1][c];
            m1[0][c] = m2[0][c]; m1[1][c] = m2[1][c];
        }
#pragma unroll
        for (int x = 0; x < 12; x++) {
            gA[0][x] = gB[0][x]; gA[1][x] = gB[1][x];
            gB[0][x] = gN[0][x]; gB[1][x] = gN[1][x];
        }
    }
    return acc;
}

__global__ __launch_bounds__(128) void gms_strip_k() {
    const int t = blockIdx.x * 128 + threadIdx.x;
    float r;   // every block lies entirely within one scale (ranges are /128)
    if (t < T0) {
        r = gms_strip<512, 512>(t, OFF0) * (1.0f / (4.0f * NB * 510.0f * 510.0f));
    } else if (t < T0 + T1) {
        r = gms_strip<256, 256>(t - T0, OFF1) * (1.0f / (4.0f * NB * 254.0f * 254.0f));
    } else if (t < T0 + T1 + T2) {
        r = gms_strip<128, 128>(t - T0 - T1, OFF2) * (1.0f / (4.0f * NB * 126.0f * 126.0f));
    } else {
        r = gms_strip<64, 64>(t - T0 - T1 - T2, OFF3) * (1.0f / (4.0f * NB * 62.0f * 62.0f));
    }
    // block reduction (4 warps)
    __shared__ float ws[4];
#pragma unroll
    for (int o = 16; o > 0; o >>= 1) r += __shfl_down_sync(0xffffffffu, r, o);
    if ((threadIdx.x & 31) == 0) ws[threadIdx.x >> 5] = r;
    __syncthreads();
    if (threadIdx.x < 4) {
        float s = ws[threadIdx.x];
        s += __shfl_down_sync(0xfu, s, 2);
        s += __shfl_down_sync(0xfu, s, 1);
        if (threadIdx.x == 0) g_partial[blockIdx.x] = (double)s;
    }
}

// ---------------------------------------------------------------------------
// Kernel 3: deterministic fixed-order reduction of per-block partials.
// ---------------------------------------------------------------------------
__global__ __launch_bounds__(256) void finalize_k(float* __restrict__ out) {
    __shared__ double ws[8];
    double s = 0.0;
    for (int i = threadIdx.x; i < NBLK; i += 256) s += g_partial[i];
#pragma unroll
    for (int o = 16; o > 0; o >>= 1) s += __shfl_down_sync(0xffffffffu, s, o);
    if ((threadIdx.x & 31) == 0) ws[threadIdx.x >> 5] = s;
    __syncthreads();
    if (threadIdx.x < 8) {
        double t = ws[threadIdx.x];
#pragma unroll
        for (int o = 4; o > 0; o >>= 1) t += __shfl_down_sync(0xffu, t, o);
        if (threadIdx.x == 0) out[0] = (float)t;
    }
}

// ---------------------------------------------------------------------------
extern "C" void kernel_launch(void* const* d_in, const int* in_sizes, int n_in,
                              void* d_out, int out_size) {
    const float* Ii = (const float*)d_in[0];
    const float* Ir = (const float*)d_in[1];
    float* out = (float*)d_out;

    graypyr_k<<<dim3(64, NB), 256>>>(Ii, Ir);
    gms_strip_k<<<NBLK, 128>>>();
    finalize_k<<<1, 256>>>(out);
}